// round 8
// baseline (speedup 1.0000x reference)
#include <cuda_runtime.h>
#include <math.h>

#define BATCH 128
#define SEQ   1024
#define INP   7
#define HID   64
#define OUTD  500
#define MTOT  (BATCH*SEQ)   // 131072
#define HSP   20

typedef unsigned long long u64;

__device__ float g_hT[(size_t)HID * MTOT];   // h transposed: g_hT[k][b*SEQ+t]

// ---- f32x2 packed helpers ----
__device__ __forceinline__ u64 pack2(float a, float b) {
    u64 r;
    asm("mov.b64 %0, {%1, %2};" : "=l"(r)
        : "r"(__float_as_uint(a)), "r"(__float_as_uint(b)));
    return r;
}
__device__ __forceinline__ u64 ffma2(u64 a, u64 b, u64 c) {
    u64 d;
    asm("fma.rn.f32x2 %0, %1, %2, %3;" : "=l"(d) : "l"(a), "l"(b), "l"(c));
    return d;
}
__device__ __forceinline__ u64 fadd2(u64 a, u64 b) {
    u64 d;
    asm("add.rn.f32x2 %0, %1, %2;" : "=l"(d) : "l"(a), "l"(b));
    return d;
}
__device__ __forceinline__ void unpack2(u64 v, float& lo, float& hi) {
    unsigned int l, h;
    asm("mov.b64 {%0, %1}, %2;" : "=r"(l), "=r"(h) : "l"(v));
    lo = __uint_as_float(l); hi = __uint_as_float(h);
}
__device__ __forceinline__ float tanhf_fast(float x) {
    float y;
    asm("tanh.approx.f32 %0, %1;" : "=f"(y) : "f"(x));
    return y;
}

// ---------------------------------------------------------------------------
// LSTM recurrence (round-3 proven core, fence-free): one CTA per batch,
// 256 threads. thread -> (hh=tid>>2, gate=tid&3). W_hh row in regs (FFMA2),
// h broadcast from smem (double buffered), gate exchange via 4-lane shuffles,
// ONE __syncthreads per step, coalesced 16-step h dumps to g_hT.
// ---------------------------------------------------------------------------
__global__ __launch_bounds__(256, 1)
void lstm_kernel(const float* __restrict__ x,
                 const float* __restrict__ W_ih,
                 const float* __restrict__ W_hh,
                 const float* __restrict__ b_ih,
                 const float* __restrict__ b_hh)
{
    __shared__ float xs[SEQ * INP];                      // 28 KB
    __shared__ __align__(16) float hbuf[2][HID];
    __shared__ __align__(16) float hstage[2][HID][HSP];  // 10 KB

    const int b    = blockIdx.x;
    const int tid  = threadIdx.x;
    const int hh   = tid >> 2;
    const int gate = tid & 3;
    const int row  = gate * HID + hh;
    const int lane = tid & 31;
    const int lb   = lane & ~3;

    {
        const float4* src = (const float4*)(x + (size_t)b * SEQ * INP);
        float4* dst = (float4*)xs;
        #pragma unroll
        for (int i = 0; i < (SEQ*INP)/(4*256); ++i)
            dst[tid + i*256] = src[tid + i*256];
    }

    u64 w2[HID/2];
    {
        const ulonglong2* wr = (const ulonglong2*)(W_hh + (size_t)row * HID);
        #pragma unroll
        for (int i = 0; i < HID/4; ++i) {
            ulonglong2 v = wr[i];
            w2[2*i+0] = v.x; w2[2*i+1] = v.y;
        }
    }
    float wih[INP];
    #pragma unroll
    for (int i = 0; i < INP; ++i) wih[i] = W_ih[row*INP + i];
    const float bias = b_ih[row] + b_hh[row];

    const float scale = (gate == 2) ? 1.0f : 0.5f;
    const float off   = (gate == 2) ? 0.0f : 0.5f;

    if (tid < HID) hbuf[0][tid] = 0.0f;
    float c = 0.0f;
    __syncthreads();

    float xacc = bias;
    #pragma unroll
    for (int i = 0; i < INP; ++i) xacc = fmaf(xs[i], wih[i], xacc);

    int cur = 0;
    for (int t = 0; t < SEQ; ++t) {
        const ulonglong2* hv = (const ulonglong2*)hbuf[cur];
        u64 a[8];
        #pragma unroll
        for (int i = 0; i < 8; ++i) a[i] = 0ull;
        #pragma unroll
        for (int j = 0; j < 4; ++j) {
            ulonglong2 h0 = hv[4*j+0];
            ulonglong2 h1 = hv[4*j+1];
            ulonglong2 h2 = hv[4*j+2];
            ulonglong2 h3 = hv[4*j+3];
            a[0] = ffma2(h0.x, w2[8*j+0], a[0]);
            a[1] = ffma2(h0.y, w2[8*j+1], a[1]);
            a[2] = ffma2(h1.x, w2[8*j+2], a[2]);
            a[3] = ffma2(h1.y, w2[8*j+3], a[3]);
            a[4] = ffma2(h2.x, w2[8*j+4], a[4]);
            a[5] = ffma2(h2.y, w2[8*j+5], a[5]);
            a[6] = ffma2(h3.x, w2[8*j+6], a[6]);
            a[7] = ffma2(h3.y, w2[8*j+7], a[7]);
        }
        u64 s0 = fadd2(a[0], a[1]);
        u64 s1 = fadd2(a[2], a[3]);
        u64 s2 = fadd2(a[4], a[5]);
        u64 s3 = fadd2(a[6], a[7]);
        u64 s  = fadd2(fadd2(s0, s1), fadd2(s2, s3));
        float slo, shi; unpack2(s, slo, shi);
        float pre = xacc + slo + shi;

        float act = fmaf(scale, tanhf_fast(scale * pre), off);

        float ig = __shfl_sync(0xffffffffu, act, lb+0);
        float fg = __shfl_sync(0xffffffffu, act, lb+1);
        float gg = __shfl_sync(0xffffffffu, act, lb+2);
        float og = __shfl_sync(0xffffffffu, act, lb+3);

        c = fmaf(fg, c, ig*gg);
        float h = og * tanhf_fast(c);
        if (gate == 0) {
            hbuf[cur^1][hh] = h;
            hstage[(t>>4)&1][hh][t & 15] = h;
        }

        int tn = (t + 1) & (SEQ - 1);
        const float* xt = xs + tn*INP;
        float xn = bias;
        #pragma unroll
        for (int i = 0; i < INP; ++i) xn = fmaf(xt[i], wih[i], xn);
        xacc = xn;

        __syncthreads();
        cur ^= 1;

        if ((t & 15) == 15) {
            int wsel = (t >> 4) & 1;
            int k = tid >> 2;
            int j = (tid & 3) * 4;
            const float* hp = &hstage[wsel][k][j];
            float4 v = make_float4(hp[0], hp[1], hp[2], hp[3]);
            *(float4*)(g_hT + (size_t)k*MTOT + (size_t)b*SEQ + (t-15) + j) = v;
        }
    }
}

// ---------------------------------------------------------------------------
// FC: out[131072, 500] = A[M,64] @ W_fc^T + b_fc
// CTA 128m x 128n, 512 threads, thread tile 8m x 4n, FFMA2 accumulators.
// B staged in smem PRE-DUPLICATED as f32x2 pairs (no pack movs in k-loop).
// B reused across MLOOP=8 m-tiles; next A tile register-prefetched.
// ---------------------------------------------------------------------------
#define FTM   128
#define FTN   128
#define MLOOP 8
#define FCT   512

__global__ __launch_bounds__(FCT, 1)
void fc_kernel(const float* __restrict__ W_fc,
               const float* __restrict__ b_fc,
               float* __restrict__ out)
{
    extern __shared__ char dynsmem[];
    float (*As)[FTM]  = (float(*)[FTM])dynsmem;                 // 32 KB
    u64   (*Bs2)[FTN] = (u64(*)[FTN])(dynsmem + HID*FTM*4);     // 64 KB

    const int tid  = threadIdx.x;
    const int tx   = tid & 31;          // n strip of 4
    const int ty   = tid >> 5;          // m strip of 8
    const int n0   = tx * 4;
    const int m0   = ty * 8;
    const int col0 = blockIdx.y * FTN;

    // ---- load B tile pre-duplicated: Bs2[k][n] = (W_fc[col0+n][k], same) ----
    {
        int n  = tid >> 2;               // 0..127
        int kq = tid & 3;
        int r  = col0 + n;
        #pragma unroll
        for (int q = 0; q < 4; ++q) {
            int kf = kq + q*4;           // float4 index 0..15
            float4 v = make_float4(0.f,0.f,0.f,0.f);
            if (r < OUTD) v = *(const float4*)(W_fc + (size_t)r*HID + kf*4);
            int kk = kf*4;
            Bs2[kk+0][n] = pack2(v.x, v.x);
            Bs2[kk+1][n] = pack2(v.y, v.y);
            Bs2[kk+2][n] = pack2(v.z, v.z);
            Bs2[kk+3][n] = pack2(v.w, v.w);
        }
    }

    const bool nvalid = (col0 + n0) < OUTD;   // 500%4==0: strip all-in/all-out

    // A-tile gather indices (thread-invariant across mt)
    const int ak[4] = { (tid)       >> 5, (tid+FCT)   >> 5,
                        (tid+2*FCT) >> 5, (tid+3*FCT) >> 5 };
    const int am    = (tid & 31) * 4;

    float4 pre[4];
    {
        const int row0 = blockIdx.x * MLOOP * FTM;
        #pragma unroll
        for (int l = 0; l < 4; ++l)
            pre[l] = *(const float4*)(g_hT + (size_t)ak[l]*MTOT + row0 + am);
    }

    for (int mt = 0; mt < MLOOP; ++mt) {
        const int row0 = (blockIdx.x * MLOOP + mt) * FTM;

        __syncthreads();   // prev compute done / B stores visible on mt=0
        #pragma unroll
        for (int l = 0; l < 4; ++l)
            *(float4*)&As[ak[l]][am] = pre[l];
        __syncthreads();

        if (mt + 1 < MLOOP) {
            const int rn = row0 + FTM;
            #pragma unroll
            for (int l = 0; l < 4; ++l)
                pre[l] = *(const float4*)(g_hT + (size_t)ak[l]*MTOT + rn + am);
        }

        u64 acc[4][4];
        #pragma unroll
        for (int mm = 0; mm < 4; ++mm)
            #pragma unroll
            for (int nn = 0; nn < 4; ++nn) acc[mm][nn] = 0ull;

        const float* asr = &As[0][m0];
        const u64*   bsr = &Bs2[0][n0];
        #pragma unroll 8
        for (int k = 0; k < HID; ++k) {
            ulonglong2 aA = *(const ulonglong2*)(asr);
            ulonglong2 aB = *(const ulonglong2*)(asr + 4);
            ulonglong2 b01 = *(const ulonglong2*)(bsr);      // n0, n0+1
            ulonglong2 b23 = *(const ulonglong2*)(bsr + 2);  // n0+2, n0+3
            asr += FTM; bsr += FTN;
            u64 b2[4] = {b01.x, b01.y, b23.x, b23.y};
            #pragma unroll
            for (int nn = 0; nn < 4; ++nn) {
                acc[0][nn] = ffma2(aA.x, b2[nn], acc[0][nn]);
                acc[1][nn] = ffma2(aA.y, b2[nn], acc[1][nn]);
                acc[2][nn] = ffma2(aB.x, b2[nn], acc[2][nn]);
                acc[3][nn] = ffma2(aB.y, b2[nn], acc[3][nn]);
            }
        }

        if (nvalid) {
            float4 bias = *(const float4*)(b_fc + col0 + n0);
            const float bb[4] = {bias.x, bias.y, bias.z, bias.w};
            #pragma unroll
            for (int mm = 0; mm < 4; ++mm) {
                float lo[4], hi[4];
                #pragma unroll
                for (int nn = 0; nn < 4; ++nn) unpack2(acc[mm][nn], lo[nn], hi[nn]);
                int r0 = row0 + m0 + 2*mm;
                float4 o0, o1;
                o0.x=lo[0]+bb[0]; o0.y=lo[1]+bb[1]; o0.z=lo[2]+bb[2]; o0.w=lo[3]+bb[3];
                o1.x=hi[0]+bb[0]; o1.y=hi[1]+bb[1]; o1.z=hi[2]+bb[2]; o1.w=hi[3]+bb[3];
                *(float4*)(out + (size_t)r0     * OUTD + col0 + n0) = o0;
                *(float4*)(out + (size_t)(r0+1) * OUTD + col0 + n0) = o1;
            }
        }
    }
}

extern "C" void kernel_launch(void* const* d_in, const int* in_sizes, int n_in,
                              void* d_out, int out_size)
{
    const float* x    = (const float*)d_in[0];
    const float* W_ih = (const float*)d_in[1];
    const float* W_hh = (const float*)d_in[2];
    const float* b_ih = (const float*)d_in[3];
    const float* b_hh = (const float*)d_in[4];
    const float* W_fc = (const float*)d_in[5];
    const float* b_fc = (const float*)d_in[6];
    float* out = (float*)d_out;

    static int smem_set = 0;
    const int dyn = 96 * 1024;    // As 32K + Bs2 64K
    if (!smem_set) {
        cudaFuncSetAttribute(fc_kernel,
                             cudaFuncAttributeMaxDynamicSharedMemorySize, dyn);
        smem_set = 1;
    }
    lstm_kernel<<<BATCH, 256>>>(x, W_ih, W_hh, b_ih, b_hh);
    fc_kernel<<<dim3(MTOT/(FTM*MLOOP), (OUTD + FTN - 1)/FTN), FCT, dyn>>>(W_fc, b_fc, out);
}

// round 9
// speedup vs baseline: 1.1399x; 1.1399x over previous
#include <cuda_runtime.h>
#include <math.h>

#define BATCH 128
#define SEQ   1024
#define INP   7
#define HID   64
#define OUTD  500
#define MTOT  (BATCH*SEQ)   // 131072
#define HSP   20

typedef unsigned long long u64;

__device__ float g_hT[(size_t)HID * MTOT];   // h transposed: g_hT[k][b*SEQ+t]

// ---- f32x2 packed helpers ----
__device__ __forceinline__ u64 pack2(float a, float b) {
    u64 r;
    asm("mov.b64 %0, {%1, %2};" : "=l"(r)
        : "r"(__float_as_uint(a)), "r"(__float_as_uint(b)));
    return r;
}
__device__ __forceinline__ u64 ffma2(u64 a, u64 b, u64 c) {
    u64 d;
    asm("fma.rn.f32x2 %0, %1, %2, %3;" : "=l"(d) : "l"(a), "l"(b), "l"(c));
    return d;
}
__device__ __forceinline__ u64 fadd2(u64 a, u64 b) {
    u64 d;
    asm("add.rn.f32x2 %0, %1, %2;" : "=l"(d) : "l"(a), "l"(b));
    return d;
}
__device__ __forceinline__ void unpack2(u64 v, float& lo, float& hi) {
    unsigned int l, h;
    asm("mov.b64 {%0, %1}, %2;" : "=r"(l), "=r"(h) : "l"(v));
    lo = __uint_as_float(l); hi = __uint_as_float(h);
}
__device__ __forceinline__ float tanhf_fast(float x) {
    float y;
    asm("tanh.approx.f32 %0, %1;" : "=f"(y) : "f"(x));
    return y;
}

// ---------------------------------------------------------------------------
// LSTM recurrence (round-3 proven core): one CTA per batch, 256 threads.
// ---------------------------------------------------------------------------
__global__ __launch_bounds__(256, 1)
void lstm_kernel(const float* __restrict__ x,
                 const float* __restrict__ W_ih,
                 const float* __restrict__ W_hh,
                 const float* __restrict__ b_ih,
                 const float* __restrict__ b_hh)
{
    __shared__ float xs[SEQ * INP];                      // 28 KB
    __shared__ __align__(16) float hbuf[2][HID];
    __shared__ __align__(16) float hstage[2][HID][HSP];  // 10 KB

    const int b    = blockIdx.x;
    const int tid  = threadIdx.x;
    const int hh   = tid >> 2;
    const int gate = tid & 3;
    const int row  = gate * HID + hh;
    const int lane = tid & 31;
    const int lb   = lane & ~3;

    {
        const float4* src = (const float4*)(x + (size_t)b * SEQ * INP);
        float4* dst = (float4*)xs;
        #pragma unroll
        for (int i = 0; i < (SEQ*INP)/(4*256); ++i)
            dst[tid + i*256] = src[tid + i*256];
    }

    u64 w2[HID/2];
    {
        const ulonglong2* wr = (const ulonglong2*)(W_hh + (size_t)row * HID);
        #pragma unroll
        for (int i = 0; i < HID/4; ++i) {
            ulonglong2 v = wr[i];
            w2[2*i+0] = v.x; w2[2*i+1] = v.y;
        }
    }
    float wih[INP];
    #pragma unroll
    for (int i = 0; i < INP; ++i) wih[i] = W_ih[row*INP + i];
    const float bias = b_ih[row] + b_hh[row];

    const float scale = (gate == 2) ? 1.0f : 0.5f;
    const float off   = (gate == 2) ? 0.0f : 0.5f;

    if (tid < HID) hbuf[0][tid] = 0.0f;
    float c = 0.0f;
    __syncthreads();

    float xacc = bias;
    #pragma unroll
    for (int i = 0; i < INP; ++i) xacc = fmaf(xs[i], wih[i], xacc);

    int cur = 0;
    for (int t = 0; t < SEQ; ++t) {
        const ulonglong2* hv = (const ulonglong2*)hbuf[cur];
        u64 a[8];
        #pragma unroll
        for (int i = 0; i < 8; ++i) a[i] = 0ull;
        #pragma unroll
        for (int j = 0; j < 4; ++j) {
            ulonglong2 h0 = hv[4*j+0];
            ulonglong2 h1 = hv[4*j+1];
            ulonglong2 h2 = hv[4*j+2];
            ulonglong2 h3 = hv[4*j+3];
            a[0] = ffma2(h0.x, w2[8*j+0], a[0]);
            a[1] = ffma2(h0.y, w2[8*j+1], a[1]);
            a[2] = ffma2(h1.x, w2[8*j+2], a[2]);
            a[3] = ffma2(h1.y, w2[8*j+3], a[3]);
            a[4] = ffma2(h2.x, w2[8*j+4], a[4]);
            a[5] = ffma2(h2.y, w2[8*j+5], a[5]);
            a[6] = ffma2(h3.x, w2[8*j+6], a[6]);
            a[7] = ffma2(h3.y, w2[8*j+7], a[7]);
        }
        u64 s0 = fadd2(a[0], a[1]);
        u64 s1 = fadd2(a[2], a[3]);
        u64 s2 = fadd2(a[4], a[5]);
        u64 s3 = fadd2(a[6], a[7]);
        u64 s  = fadd2(fadd2(s0, s1), fadd2(s2, s3));
        float slo, shi; unpack2(s, slo, shi);
        float pre = xacc + slo + shi;

        float act = fmaf(scale, tanhf_fast(scale * pre), off);

        float ig = __shfl_sync(0xffffffffu, act, lb+0);
        float fg = __shfl_sync(0xffffffffu, act, lb+1);
        float gg = __shfl_sync(0xffffffffu, act, lb+2);
        float og = __shfl_sync(0xffffffffu, act, lb+3);

        c = fmaf(fg, c, ig*gg);
        float h = og * tanhf_fast(c);
        if (gate == 0) {
            hbuf[cur^1][hh] = h;
            hstage[(t>>4)&1][hh][t & 15] = h;
        }

        int tn = (t + 1) & (SEQ - 1);
        const float* xt = xs + tn*INP;
        float xn = bias;
        #pragma unroll
        for (int i = 0; i < INP; ++i) xn = fmaf(xt[i], wih[i], xn);
        xacc = xn;

        __syncthreads();
        cur ^= 1;

        if ((t & 15) == 15) {
            int wsel = (t >> 4) & 1;
            int k = tid >> 2;
            int j = (tid & 3) * 4;
            const float* hp = &hstage[wsel][k][j];
            float4 v = make_float4(hp[0], hp[1], hp[2], hp[3]);
            *(float4*)(g_hT + (size_t)k*MTOT + (size_t)b*SEQ + (t-15) + j) = v;
        }
    }
}

// ---------------------------------------------------------------------------
// FC: out[131072, 500] = A[M,64] @ W_fc^T + b_fc
// CTA 128m x 128n, 256 threads, thread tile 8m x 8n.
// A duplicated in smem as (m,m) f32x2 pairs (BROADCAST reads -> free dup).
// B plain floats: consecutive-n pairs are natively packed f32x2.
// k-loop = 6 LDS.128 + 32 FFMA2, zero pack movs.
// ---------------------------------------------------------------------------
#define FTM   128
#define FTN   128
#define MLOOP 8
#define FCT   256

__global__ __launch_bounds__(FCT, 1)
void fc_kernel(const float* __restrict__ W_fc,
               const float* __restrict__ b_fc,
               float* __restrict__ out)
{
    extern __shared__ char dynsmem[];
    u64   (*As2)[FTM] = (u64(*)[FTM])dynsmem;                    // 64 KB [k][m] dup
    float (*Bs)[FTN]  = (float(*)[FTN])(dynsmem + HID*FTM*8);    // 32 KB [k][n]

    const int tid  = threadIdx.x;
    const int tx   = tid & 15;           // n strip: n0 = tx*8
    const int ty   = tid >> 4;           // m strip: m0 = ty*8
    const int n0   = tx * 8;
    const int m0   = ty * 8;
    const int col0 = blockIdx.y * FTN;

    // ---- B tile (plain): Bs[k][n] = W_fc[col0+n][k] ----
    {
        int n  = tid >> 1;               // 0..127
        int kh = tid & 1;
        int r  = col0 + n;
        #pragma unroll
        for (int q = 0; q < 8; ++q) {
            int kf = kh*8 + q;           // float4 index 0..15
            float4 v = make_float4(0.f,0.f,0.f,0.f);
            if (r < OUTD) v = *(const float4*)(W_fc + (size_t)r*HID + kf*4);
            int kk = kf*4;
            Bs[kk+0][n] = v.x;
            Bs[kk+1][n] = v.y;
            Bs[kk+2][n] = v.z;
            Bs[kk+3][n] = v.w;
        }
    }

    // A gather indices (thread-invariant): 8 chunks of the 64x128 tile
    int ak[8], am;
    #pragma unroll
    for (int l = 0; l < 8; ++l) ak[l] = (tid + l*FCT) >> 5;   // k = 0..63
    am = (tid & 31) * 4;                                       // m4

    float4 pre[8];
    {
        const int row0 = blockIdx.x * MLOOP * FTM;
        #pragma unroll
        for (int l = 0; l < 8; ++l)
            pre[l] = *(const float4*)(g_hT + (size_t)ak[l]*MTOT + row0 + am);
    }

    // epilogue column predicates (n strips of 8 may straddle 500)
    const int gn0 = col0 + n0;
    const bool v0 = (gn0 + 3)  < OUTD + 1 && gn0 + 3 <= 499;  // gn0 <= 496
    const bool v1 = (gn0 + 7) <= 499;                          // gn0 <= 492

    for (int mt = 0; mt < MLOOP; ++mt) {
        const int row0 = (blockIdx.x * MLOOP + mt) * FTM;

        __syncthreads();   // prev compute done / B stores visible on mt=0
        #pragma unroll
        for (int l = 0; l < 8; ++l) {
            ulonglong2 d0, d1;
            d0.x = pack2(pre[l].x, pre[l].x);
            d0.y = pack2(pre[l].y, pre[l].y);
            d1.x = pack2(pre[l].z, pre[l].z);
            d1.y = pack2(pre[l].w, pre[l].w);
            *(ulonglong2*)&As2[ak[l]][am + 0] = d0;
            *(ulonglong2*)&As2[ak[l]][am + 2] = d1;
        }
        __syncthreads();

        if (mt + 1 < MLOOP) {
            const int rn = row0 + FTM;
            #pragma unroll
            for (int l = 0; l < 8; ++l)
                pre[l] = *(const float4*)(g_hT + (size_t)ak[l]*MTOT + rn + am);
        }

        u64 acc[8][4];
        #pragma unroll
        for (int mm = 0; mm < 8; ++mm)
            #pragma unroll
            for (int p = 0; p < 4; ++p) acc[mm][p] = 0ull;

        const u64*   asr = &As2[0][m0];
        const float* bsr = &Bs[0][n0];
        #pragma unroll 4
        for (int k = 0; k < HID; ++k) {
            ulonglong2 a01 = *(const ulonglong2*)(asr + 0);  // (m0,m0) (m0+1,m0+1)
            ulonglong2 a23 = *(const ulonglong2*)(asr + 2);
            ulonglong2 a45 = *(const ulonglong2*)(asr + 4);
            ulonglong2 a67 = *(const ulonglong2*)(asr + 6);
            ulonglong2 b01 = *(const ulonglong2*)(bsr + 0);  // (n0,n0+1) (n0+2,n0+3)
            ulonglong2 b45 = *(const ulonglong2*)(bsr + 4);  // (n0+4,n0+5) (n0+6,n0+7)
            asr += FTM; bsr += FTN;
            u64 ad[8] = {a01.x,a01.y,a23.x,a23.y,a45.x,a45.y,a67.x,a67.y};
            u64 bp[4] = {b01.x,b01.y,b45.x,b45.y};
            #pragma unroll
            for (int p = 0; p < 4; ++p) {
                #pragma unroll
                for (int mm = 0; mm < 8; ++mm)
                    acc[mm][p] = ffma2(ad[mm], bp[p], acc[mm][p]);
            }
        }

        // epilogue: acc[mm][p] holds (n0+2p, n0+2p+1) for row m0+mm
        float4 bias0 = make_float4(0.f,0.f,0.f,0.f);
        float4 bias1 = make_float4(0.f,0.f,0.f,0.f);
        if (v0) bias0 = *(const float4*)(b_fc + gn0);
        if (v1) bias1 = *(const float4*)(b_fc + gn0 + 4);
        #pragma unroll
        for (int mm = 0; mm < 8; ++mm) {
            int r = row0 + m0 + mm;
            float* orow = out + (size_t)r * OUTD + gn0;
            float lo0,hi0, lo1,hi1, lo2,hi2, lo3,hi3;
            unpack2(acc[mm][0], lo0, hi0);
            unpack2(acc[mm][1], lo1, hi1);
            unpack2(acc[mm][2], lo2, hi2);
            unpack2(acc[mm][3], lo3, hi3);
            if (v0) {
                float4 o;
                o.x = lo0 + bias0.x; o.y = hi0 + bias0.y;
                o.z = lo1 + bias0.z; o.w = hi1 + bias0.w;
                *(float4*)(orow) = o;
            }
            if (v1) {
                float4 o;
                o.x = lo2 + bias1.x; o.y = hi2 + bias1.y;
                o.z = lo3 + bias1.z; o.w = hi3 + bias1.w;
                *(float4*)(orow + 4) = o;
            }
        }
    }
}

extern "C" void kernel_launch(void* const* d_in, const int* in_sizes, int n_in,
                              void* d_out, int out_size)
{
    const float* x    = (const float*)d_in[0];
    const float* W_ih = (const float*)d_in[1];
    const float* W_hh = (const float*)d_in[2];
    const float* b_ih = (const float*)d_in[3];
    const float* b_hh = (const float*)d_in[4];
    const float* W_fc = (const float*)d_in[5];
    const float* b_fc = (const float*)d_in[6];
    float* out = (float*)d_out;

    static int smem_set = 0;
    const int dyn = 96 * 1024;    // As2 64K + Bs 32K
    if (!smem_set) {
        cudaFuncSetAttribute(fc_kernel,
                             cudaFuncAttributeMaxDynamicSharedMemorySize, dyn);
        smem_set = 1;
    }
    lstm_kernel<<<BATCH, 256>>>(x, W_ih, W_hh, b_ih, b_hh);
    fc_kernel<<<dim3(MTOT/(FTM*MLOOP), (OUTD + FTN - 1)/FTN), FCT, dyn>>>(W_fc, b_fc, out);
}

// round 10
// speedup vs baseline: 1.5372x; 1.3485x over previous
#include <cuda_runtime.h>
#include <math.h>

#define BATCH 128
#define SEQ   1024
#define INP   7
#define HID   64
#define OUTD  500
#define MTOT  (BATCH*SEQ)   // 131072
#define HSP   20

typedef unsigned long long u64;
typedef unsigned int u32;

__device__ float g_hT[(size_t)HID * MTOT];   // h transposed: g_hT[k][b*SEQ+t]

// ---- f32x2 packed helpers (lstm) ----
__device__ __forceinline__ u64 ffma2(u64 a, u64 b, u64 c) {
    u64 d;
    asm("fma.rn.f32x2 %0, %1, %2, %3;" : "=l"(d) : "l"(a), "l"(b), "l"(c));
    return d;
}
__device__ __forceinline__ u64 fadd2(u64 a, u64 b) {
    u64 d;
    asm("add.rn.f32x2 %0, %1, %2;" : "=l"(d) : "l"(a), "l"(b));
    return d;
}
__device__ __forceinline__ void unpack2(u64 v, float& lo, float& hi) {
    u32 l, h;
    asm("mov.b64 {%0, %1}, %2;" : "=r"(l), "=r"(h) : "l"(v));
    lo = __uint_as_float(l); hi = __uint_as_float(h);
}
__device__ __forceinline__ float tanhf_fast(float x) {
    float y;
    asm("tanh.approx.f32 %0, %1;" : "=f"(y) : "f"(x));
    return y;
}
// ---- tf32 helpers (fc) ----
__device__ __forceinline__ u32 cvt_tf32(float x) {
    u32 r; asm("cvt.rna.tf32.f32 %0, %1;" : "=r"(r) : "f"(x)); return r;
}
__device__ __forceinline__ void mma_tf32(float* d,
    u32 a0, u32 a1, u32 a2, u32 a3, u32 b0, u32 b1)
{
    asm volatile(
        "mma.sync.aligned.m16n8k8.row.col.f32.tf32.tf32.f32 "
        "{%0,%1,%2,%3}, {%4,%5,%6,%7}, {%8,%9}, {%0,%1,%2,%3};"
        : "+f"(d[0]), "+f"(d[1]), "+f"(d[2]), "+f"(d[3])
        : "r"(a0), "r"(a1), "r"(a2), "r"(a3), "r"(b0), "r"(b1));
}

// ---------------------------------------------------------------------------
// LSTM recurrence (proven core): one CTA per batch, 256 threads.
// ---------------------------------------------------------------------------
__global__ __launch_bounds__(256, 1)
void lstm_kernel(const float* __restrict__ x,
                 const float* __restrict__ W_ih,
                 const float* __restrict__ W_hh,
                 const float* __restrict__ b_ih,
                 const float* __restrict__ b_hh)
{
    __shared__ float xs[SEQ * INP];                      // 28 KB
    __shared__ __align__(16) float hbuf[2][HID];
    __shared__ __align__(16) float hstage[2][HID][HSP];  // 10 KB

    const int b    = blockIdx.x;
    const int tid  = threadIdx.x;
    const int hh   = tid >> 2;
    const int gate = tid & 3;
    const int row  = gate * HID + hh;
    const int lane = tid & 31;
    const int lb   = lane & ~3;

    {
        const float4* src = (const float4*)(x + (size_t)b * SEQ * INP);
        float4* dst = (float4*)xs;
        #pragma unroll
        for (int i = 0; i < (SEQ*INP)/(4*256); ++i)
            dst[tid + i*256] = src[tid + i*256];
    }

    u64 w2[HID/2];
    {
        const ulonglong2* wr = (const ulonglong2*)(W_hh + (size_t)row * HID);
        #pragma unroll
        for (int i = 0; i < HID/4; ++i) {
            ulonglong2 v = wr[i];
            w2[2*i+0] = v.x; w2[2*i+1] = v.y;
        }
    }
    float wih[INP];
    #pragma unroll
    for (int i = 0; i < INP; ++i) wih[i] = W_ih[row*INP + i];
    const float bias = b_ih[row] + b_hh[row];

    const float scale = (gate == 2) ? 1.0f : 0.5f;
    const float off   = (gate == 2) ? 0.0f : 0.5f;

    if (tid < HID) hbuf[0][tid] = 0.0f;
    float c = 0.0f;
    __syncthreads();

    float xacc = bias;
    #pragma unroll
    for (int i = 0; i < INP; ++i) xacc = fmaf(xs[i], wih[i], xacc);

    int cur = 0;
    for (int t = 0; t < SEQ; ++t) {
        const ulonglong2* hv = (const ulonglong2*)hbuf[cur];
        u64 a[8];
        #pragma unroll
        for (int i = 0; i < 8; ++i) a[i] = 0ull;
        #pragma unroll
        for (int j = 0; j < 4; ++j) {
            ulonglong2 h0 = hv[4*j+0];
            ulonglong2 h1 = hv[4*j+1];
            ulonglong2 h2 = hv[4*j+2];
            ulonglong2 h3 = hv[4*j+3];
            a[0] = ffma2(h0.x, w2[8*j+0], a[0]);
            a[1] = ffma2(h0.y, w2[8*j+1], a[1]);
            a[2] = ffma2(h1.x, w2[8*j+2], a[2]);
            a[3] = ffma2(h1.y, w2[8*j+3], a[3]);
            a[4] = ffma2(h2.x, w2[8*j+4], a[4]);
            a[5] = ffma2(h2.y, w2[8*j+5], a[5]);
            a[6] = ffma2(h3.x, w2[8*j+6], a[6]);
            a[7] = ffma2(h3.y, w2[8*j+7], a[7]);
        }
        u64 s0 = fadd2(a[0], a[1]);
        u64 s1 = fadd2(a[2], a[3]);
        u64 s2 = fadd2(a[4], a[5]);
        u64 s3 = fadd2(a[6], a[7]);
        u64 s  = fadd2(fadd2(s0, s1), fadd2(s2, s3));
        float slo, shi; unpack2(s, slo, shi);
        float pre = xacc + slo + shi;

        float act = fmaf(scale, tanhf_fast(scale * pre), off);

        float ig = __shfl_sync(0xffffffffu, act, lb+0);
        float fg = __shfl_sync(0xffffffffu, act, lb+1);
        float gg = __shfl_sync(0xffffffffu, act, lb+2);
        float og = __shfl_sync(0xffffffffu, act, lb+3);

        c = fmaf(fg, c, ig*gg);
        float h = og * tanhf_fast(c);
        if (gate == 0) {
            hbuf[cur^1][hh] = h;
            hstage[(t>>4)&1][hh][t & 15] = h;
        }

        int tn = (t + 1) & (SEQ - 1);
        const float* xt = xs + tn*INP;
        float xn = bias;
        #pragma unroll
        for (int i = 0; i < INP; ++i) xn = fmaf(xt[i], wih[i], xn);
        xacc = xn;

        __syncthreads();
        cur ^= 1;

        if ((t & 15) == 15) {
            int wsel = (t >> 4) & 1;
            int k = tid >> 2;
            int j = (tid & 3) * 4;
            const float* hp = &hstage[wsel][k][j];
            float4 v = make_float4(hp[0], hp[1], hp[2], hp[3]);
            *(float4*)(g_hT + (size_t)k*MTOT + (size_t)b*SEQ + (t-15) + j) = v;
        }
    }
}

// ---------------------------------------------------------------------------
// FC on tensor cores: out[131072,500] = A[M,64] @ W_fc^T + b_fc, tf32 MMA.
// CTA 256 thr / 8 warps, tile 128m x 64n, MLOOP=8 m-tiles per B stage.
// A staged [k][m] stride 136 (per-fragment LDS.32 conflict-free).
// B pre-swizzled into per-(kstep,jj,lane) uint4 fragments: 1 LDS.128 / 2 MMA.
// ---------------------------------------------------------------------------
#define AST   136      // A smem row stride (floats): 136 % 32 == 8 -> no conflicts
#define MLOOP 8

__global__ __launch_bounds__(256, 1)
void fc_mma_kernel(const float* __restrict__ W_fc,
                   const float* __restrict__ b_fc,
                   float* __restrict__ out)
{
    extern __shared__ u32 smemu[];
    u32*   As  = smemu;                        // [64][AST] tf32 bits, 34816 B
    uint4* Bs4 = (uint4*)(smemu + HID*AST);    // [8][4][32] fragments, 16384 B

    const int tid  = threadIdx.x;
    const int lane = tid & 31;
    const int warp = tid >> 5;                 // m-fragment row: m0 = 16*warp
    const int lg   = lane >> 2;                // groupID
    const int lt   = lane & 3;                 // threadID_in_group
    const int col0 = blockIdx.y * 64;
    const int ROW0 = blockIdx.x * (128 * MLOOP);

    // ---- stage B fragments (once per CTA) ----
    #pragma unroll
    for (int q = 0; q < 4; ++q) {
        int idx = tid + q*256;                 // 0..1023
        int bl  = idx & 31;
        int jj  = (idx >> 5) & 3;
        int s   = idx >> 7;
        int kA  = s*8 + (bl & 3);
        int n1  = col0 + jj*16 + (bl >> 2);
        int n2  = n1 + 8;
        float fx=0.f, fy=0.f, fz=0.f, fw=0.f;
        if (n1 < OUTD) { fx = W_fc[n1*HID + kA]; fy = W_fc[n1*HID + kA + 4]; }
        if (n2 < OUTD) { fz = W_fc[n2*HID + kA]; fw = W_fc[n2*HID + kA + 4]; }
        Bs4[(s*4 + jj)*32 + bl] =
            make_uint4(cvt_tf32(fx), cvt_tf32(fy), cvt_tf32(fz), cvt_tf32(fw));
    }

    // bias per n-fragment (col pairs are even-aligned; 500 even -> all-or-none)
    float2 biasj[8];
    #pragma unroll
    for (int j = 0; j < 8; ++j) {
        int nj = col0 + j*8 + lt*2;
        if (nj < OUTD) { biasj[j].x = b_fc[nj]; biasj[j].y = b_fc[nj+1]; }
        else           { biasj[j].x = 0.f;      biasj[j].y = 0.f; }
    }

    // A gather indices (thread-invariant): 2048 float4 slots over [64k][128m]
    int ak[8];
    #pragma unroll
    for (int l = 0; l < 8; ++l) ak[l] = (tid + l*256) >> 5;   // k row
    const int am = (tid & 31) * 4;                             // m offset

    float4 pre[8];
    #pragma unroll
    for (int l = 0; l < 8; ++l)
        pre[l] = *(const float4*)(g_hT + (size_t)ak[l]*MTOT + ROW0 + am);

    for (int mt = 0; mt < MLOOP; ++mt) {
        __syncthreads();   // prev compute done / B visible on mt=0
        #pragma unroll
        for (int l = 0; l < 8; ++l) {
            uint4 v = make_uint4(cvt_tf32(pre[l].x), cvt_tf32(pre[l].y),
                                 cvt_tf32(pre[l].z), cvt_tf32(pre[l].w));
            *(uint4*)&As[ak[l]*AST + am] = v;
        }
        __syncthreads();

        if (mt + 1 < MLOOP) {
            const int rn = ROW0 + (mt+1)*128;
            #pragma unroll
            for (int l = 0; l < 8; ++l)
                pre[l] = *(const float4*)(g_hT + (size_t)ak[l]*MTOT + rn + am);
        }

        float d[8][4];
        #pragma unroll
        for (int j = 0; j < 8; ++j)
            #pragma unroll
            for (int p = 0; p < 4; ++p) d[j][p] = 0.f;

        #pragma unroll
        for (int s = 0; s < 8; ++s) {
            const int ka = s*8 + lt;
            const int mb = 16*warp + lg;
            u32 a0 = As[ ka      *AST + mb    ];
            u32 a1 = As[ ka      *AST + mb + 8];
            u32 a2 = As[(ka + 4) *AST + mb    ];
            u32 a3 = As[(ka + 4) *AST + mb + 8];
            #pragma unroll
            for (int jj = 0; jj < 4; ++jj) {
                uint4 bb = Bs4[(s*4 + jj)*32 + lane];
                mma_tf32(d[2*jj  ], a0, a1, a2, a3, bb.x, bb.y);
                mma_tf32(d[2*jj+1], a0, a1, a2, a3, bb.z, bb.w);
            }
        }

        // epilogue: d[j] = rows (r0, r0+8), cols (nj, nj+1)
        const int r0 = ROW0 + mt*128 + 16*warp + lg;
        float* o0 = out + (size_t)r0 * OUTD;
        float* o1 = o0 + 8 * OUTD;
        #pragma unroll
        for (int j = 0; j < 8; ++j) {
            int nj = col0 + j*8 + lt*2;
            if (nj < OUTD) {
                float2 v0, v1;
                v0.x = d[j][0] + biasj[j].x;  v0.y = d[j][1] + biasj[j].y;
                v1.x = d[j][2] + biasj[j].x;  v1.y = d[j][3] + biasj[j].y;
                *(float2*)(o0 + nj) = v0;
                *(float2*)(o1 + nj) = v1;
            }
        }
    }
}

extern "C" void kernel_launch(void* const* d_in, const int* in_sizes, int n_in,
                              void* d_out, int out_size)
{
    const float* x    = (const float*)d_in[0];
    const float* W_ih = (const float*)d_in[1];
    const float* W_hh = (const float*)d_in[2];
    const float* b_ih = (const float*)d_in[3];
    const float* b_hh = (const float*)d_in[4];
    const float* W_fc = (const float*)d_in[5];
    const float* b_fc = (const float*)d_in[6];
    float* out = (float*)d_out;

    static int smem_set = 0;
    const int dyn = (HID*AST*4) + (8*4*32*16);   // 34816 + 16384 = 51200 B
    if (!smem_set) {
        cudaFuncSetAttribute(fc_mma_kernel,
                             cudaFuncAttributeMaxDynamicSharedMemorySize, dyn);
        smem_set = 1;
    }
    lstm_kernel<<<BATCH, 256>>>(x, W_ih, W_hh, b_ih, b_hh);
    fc_mma_kernel<<<dim3(MTOT/(128*MLOOP), 8), 256, dyn>>>(W_fc, b_fc, out);
}